// round 1
// baseline (speedup 1.0000x reference)
#include <cuda_runtime.h>

#define DEV_INLINE __device__ __forceinline__

constexpr int N  = 131072;
constexpr int C  = 128;
constexpr int S  = 6;
constexpr int E  = 131072;
constexpr int EL = 32768;
constexpr int NB = 4;
constexpr int CC = C * C;

// Scratch (allocation-free rule: static __device__ arrays)
__device__ float g_feat[N * C];   // current feat (== identity at block entry)
__device__ float g_temp[N * C];   // temp accumulator / Y2
__device__ float g_Y[N * C];      // per-scale GEMM output / feat_mid

// ---------------------------------------------------------------------------
// packed fp32x2 helpers (Blackwell native; 2 fp32 FMA per instruction)
// ---------------------------------------------------------------------------
DEV_INLINE unsigned long long ffma2(unsigned long long a, unsigned long long b,
                                    unsigned long long c) {
  unsigned long long d;
  asm("fma.rn.f32x2 %0, %1, %2, %3;" : "=l"(d) : "l"(a), "l"(b), "l"(c));
  return d;
}
DEV_INLINE unsigned long long splat2(float x) {
  unsigned long long d;
  unsigned int xi = __float_as_uint(x);
  asm("mov.b64 %0, {%1, %1};" : "=l"(d) : "r"(xi));
  return d;
}

// ---------------------------------------------------------------------------
// GEMM: Out[N,128] = A[N,128] @ W[128,128]   (row-major everywhere)
// Block: 256 threads, 64 rows. Thread: 8 rows x 4 cols, f32x2 over col pairs.
// ---------------------------------------------------------------------------
constexpr int AS_PITCH = 132;  // 128 + 4 pad (keeps float4 alignment: 132*4=33*16)
constexpr int SMEM_GEMM_BYTES = (64 * AS_PITCH + 128 * 128) * 4;

__global__ void __launch_bounds__(256, 2) gemm128_kernel(
    const float* __restrict__ A, const float* __restrict__ W,
    float* __restrict__ Out) {
  extern __shared__ __align__(16) float smem[];
  float* As = smem;                  // [64][AS_PITCH]
  float* Ws = smem + 64 * AS_PITCH;  // [128][128]
  const int tid = threadIdx.x;
  const int rowBase = blockIdx.x * 64;

  // Stage A tile (64x128) into padded smem, row-major.
#pragma unroll
  for (int t = 0; t < 8; ++t) {
    int idx = tid + t * 256;
    int r = idx >> 5, k4 = idx & 31;
    float4 a = *(const float4*)(A + (size_t)(rowBase + r) * C + k4 * 4);
    *(float4*)(As + r * AS_PITCH + k4 * 4) = a;
  }
  // Stage W (128x128).
#pragma unroll
  for (int t = 0; t < 16; ++t) {
    int lin = tid + t * 256;
    *(float4*)(Ws + lin * 4) = *(const float4*)(W + lin * 4);
  }
  __syncthreads();

  const int tx = tid & 31;   // col group: cols 4*tx..4*tx+3
  const int ty = tid >> 5;   // row group: rows ty*8..ty*8+7

  unsigned long long acc[8][2];
#pragma unroll
  for (int r = 0; r < 8; ++r) { acc[r][0] = 0ull; acc[r][1] = 0ull; }

  const float* aBase = As + (ty * 8) * AS_PITCH;

#pragma unroll 2
  for (int kk = 0; kk < 32; ++kk) {
    float4 a4[8];
#pragma unroll
    for (int r = 0; r < 8; ++r)
      a4[r] = *(const float4*)(aBase + r * AS_PITCH + kk * 4);
#pragma unroll
    for (int j = 0; j < 4; ++j) {
      const int k = kk * 4 + j;
      ulonglong2 w = *(const ulonglong2*)(Ws + k * 128 + tx * 4);
#pragma unroll
      for (int r = 0; r < 8; ++r) {
        float av = (j == 0) ? a4[r].x : (j == 1) ? a4[r].y
                 : (j == 2) ? a4[r].z : a4[r].w;
        unsigned long long a2 = splat2(av);
        acc[r][0] = ffma2(a2, w.x, acc[r][0]);
        acc[r][1] = ffma2(a2, w.y, acc[r][1]);
      }
    }
  }

#pragma unroll
  for (int r = 0; r < 8; ++r) {
    float2 p0 = *(float2*)&acc[r][0];
    float2 p1 = *(float2*)&acc[r][1];
    float4 o = make_float4(p0.x, p0.y, p1.x, p1.y);
    int row = rowBase + ty * 8 + r;
    *(float4*)(Out + (size_t)row * C + tx * 4) = o;
  }
}

// ---------------------------------------------------------------------------
// Input MLP first layer: H[n,c] = relu(X[n,0]*W0[0,c] + X[n,1]*W0[1,c] + B0[c])
// ---------------------------------------------------------------------------
__global__ void mlp0_kernel(const float* __restrict__ X2,
                            const float* __restrict__ W0,
                            const float* __restrict__ B0,
                            float* __restrict__ H) {
  int idx = blockIdx.x * blockDim.x + threadIdx.x;  // n*C + c
  int n = idx >> 7, c = idx & 127;
  float x0 = X2[2 * n], x1 = X2[2 * n + 1];
  float h = fmaf(x0, W0[c], fmaf(x1, W0[C + c], B0[c]));
  H[idx] = fmaxf(h, 0.0f);
}

// ---------------------------------------------------------------------------
// Scatter: T[u[e], :] += Y[v[e], :]   (warp per edge, red.global.add.v4.f32)
// ---------------------------------------------------------------------------
__global__ void scatter_kernel(const float* __restrict__ Y,
                               const int* __restrict__ u,
                               const int* __restrict__ v, int nE,
                               float* __restrict__ T) {
  int e = (blockIdx.x * blockDim.x + threadIdx.x) >> 5;
  if (e >= nE) return;
  int lane = threadIdx.x & 31;
  int src = __ldg(&v[e]);
  int dst = __ldg(&u[e]);
  float4 val = ((const float4*)(Y + (size_t)src * C))[lane];
  float* p = T + (size_t)dst * C + lane * 4;
  asm volatile("red.global.add.v4.f32 [%0], {%1, %2, %3, %4};"
               :: "l"(p), "f"(val.x), "f"(val.y), "f"(val.z), "f"(val.w)
               : "memory");
}

// ---------------------------------------------------------------------------
// Row-wise GroupNorm helpers (warp per row, 4 channels per lane)
// ---------------------------------------------------------------------------
DEV_INLINE float wsum(float v) {
#pragma unroll
  for (int o = 16; o > 0; o >>= 1) v += __shfl_xor_sync(0xffffffffu, v, o);
  return v;
}

// O = relu(GN(X, g, b))
__global__ void gn_relu_kernel(const float* __restrict__ X,
                               const float* __restrict__ G,
                               const float* __restrict__ Bt,
                               float* __restrict__ O) {
  int w = (blockIdx.x * blockDim.x + threadIdx.x) >> 5;
  int lane = threadIdx.x & 31;
  float4 x = ((const float4*)X)[(size_t)w * 32 + lane];
  float s = x.x + x.y + x.z + x.w;
  float q = x.x * x.x + x.y * x.y + x.z * x.z + x.w * x.w;
  s = wsum(s); q = wsum(q);
  float mu = s * (1.0f / 128.0f);
  float var = q * (1.0f / 128.0f) - mu * mu;
  float rs = rsqrtf(var + 1e-5f);
  float4 g = ((const float4*)G)[lane];
  float4 b = ((const float4*)Bt)[lane];
  float4 o;
  o.x = fmaxf((x.x - mu) * rs * g.x + b.x, 0.0f);
  o.y = fmaxf((x.y - mu) * rs * g.y + b.y, 0.0f);
  o.z = fmaxf((x.z - mu) * rs * g.z + b.z, 0.0f);
  o.w = fmaxf((x.w - mu) * rs * g.w + b.w, 0.0f);
  ((float4*)O)[(size_t)w * 32 + lane] = o;
}

// O = relu(GN(X, g, b) + Id)
__global__ void gn_res_relu_kernel(const float* __restrict__ X,
                                   const float* __restrict__ G,
                                   const float* __restrict__ Bt,
                                   const float* __restrict__ Id,
                                   float* __restrict__ O) {
  int w = (blockIdx.x * blockDim.x + threadIdx.x) >> 5;
  int lane = threadIdx.x & 31;
  float4 x = ((const float4*)X)[(size_t)w * 32 + lane];
  float s = x.x + x.y + x.z + x.w;
  float q = x.x * x.x + x.y * x.y + x.z * x.z + x.w * x.w;
  s = wsum(s); q = wsum(q);
  float mu = s * (1.0f / 128.0f);
  float var = q * (1.0f / 128.0f) - mu * mu;
  float rs = rsqrtf(var + 1e-5f);
  float4 g = ((const float4*)G)[lane];
  float4 b = ((const float4*)Bt)[lane];
  float4 id = ((const float4*)Id)[(size_t)w * 32 + lane];
  float4 o;
  o.x = fmaxf((x.x - mu) * rs * g.x + b.x + id.x, 0.0f);
  o.y = fmaxf((x.y - mu) * rs * g.y + b.y + id.y, 0.0f);
  o.z = fmaxf((x.z - mu) * rs * g.z + b.z + id.z, 0.0f);
  o.w = fmaxf((x.w - mu) * rs * g.w + b.w + id.w, 0.0f);
  ((float4*)O)[(size_t)w * 32 + lane] = o;
}

// O = relu(GN(Y1,g1,b1) + GN(Y2,g2,b2))
__global__ void combine_kernel(const float* __restrict__ Y1,
                               const float* __restrict__ Y2,
                               const float* __restrict__ G1,
                               const float* __restrict__ B1,
                               const float* __restrict__ G2,
                               const float* __restrict__ B2,
                               float* __restrict__ O) {
  int w = (blockIdx.x * blockDim.x + threadIdx.x) >> 5;
  int lane = threadIdx.x & 31;
  float4 x1 = ((const float4*)Y1)[(size_t)w * 32 + lane];
  float4 x2 = ((const float4*)Y2)[(size_t)w * 32 + lane];
  float s1 = x1.x + x1.y + x1.z + x1.w;
  float q1 = x1.x * x1.x + x1.y * x1.y + x1.z * x1.z + x1.w * x1.w;
  float s2 = x2.x + x2.y + x2.z + x2.w;
  float q2 = x2.x * x2.x + x2.y * x2.y + x2.z * x2.z + x2.w * x2.w;
  s1 = wsum(s1); q1 = wsum(q1);
  s2 = wsum(s2); q2 = wsum(q2);
  float mu1 = s1 * (1.0f / 128.0f);
  float rs1 = rsqrtf(q1 * (1.0f / 128.0f) - mu1 * mu1 + 1e-5f);
  float mu2 = s2 * (1.0f / 128.0f);
  float rs2 = rsqrtf(q2 * (1.0f / 128.0f) - mu2 * mu2 + 1e-5f);
  float4 g1 = ((const float4*)G1)[lane];
  float4 b1 = ((const float4*)B1)[lane];
  float4 g2 = ((const float4*)G2)[lane];
  float4 b2 = ((const float4*)B2)[lane];
  float4 o;
  o.x = fmaxf((x1.x - mu1) * rs1 * g1.x + b1.x + (x2.x - mu2) * rs2 * g2.x + b2.x, 0.0f);
  o.y = fmaxf((x1.y - mu1) * rs1 * g1.y + b1.y + (x2.y - mu2) * rs2 * g2.y + b2.y, 0.0f);
  o.z = fmaxf((x1.z - mu1) * rs1 * g1.z + b1.z + (x2.z - mu2) * rs2 * g2.z + b2.z, 0.0f);
  o.w = fmaxf((x1.w - mu1) * rs1 * g1.w + b1.w + (x2.w - mu2) * rs2 * g2.w + b2.w, 0.0f);
  ((float4*)O)[(size_t)w * 32 + lane] = o;
}

// ---------------------------------------------------------------------------
extern "C" void kernel_launch(void* const* d_in, const int* in_sizes, int n_in,
                              void* d_out, int out_size) {
  const float* ctrs   = (const float*)d_in[0];
  const float* feats  = (const float*)d_in[1];
  const int*   pre_u  = (const int*)d_in[2];
  const int*   pre_v  = (const int*)d_in[3];
  const int*   suc_u  = (const int*)d_in[4];
  const int*   suc_v  = (const int*)d_in[5];
  const int*   left_u = (const int*)d_in[6];
  const int*   left_v = (const int*)d_in[7];
  const int*   right_u= (const int*)d_in[8];
  const int*   right_v= (const int*)d_in[9];
  const float* ic_w0  = (const float*)d_in[10];
  const float* ic_b0  = (const float*)d_in[11];
  const float* ic_w1  = (const float*)d_in[12];
  const float* ic_g   = (const float*)d_in[13];
  const float* ic_bt  = (const float*)d_in[14];
  const float* if_w0  = (const float*)d_in[15];
  const float* if_b0  = (const float*)d_in[16];
  const float* if_w1  = (const float*)d_in[17];
  const float* if_g   = (const float*)d_in[18];
  const float* if_bt  = (const float*)d_in[19];
  const float* ctr_w  = (const float*)d_in[20];
  const float* pre_w  = (const float*)d_in[21];
  const float* suc_w  = (const float*)d_in[22];
  const float* left_w = (const float*)d_in[23];
  const float* right_w= (const float*)d_in[24];
  const float* norm_g = (const float*)d_in[25];
  const float* norm_b = (const float*)d_in[26];
  const float* ctr2_w = (const float*)d_in[27];
  const float* ctr2_g = (const float*)d_in[28];
  const float* ctr2_b = (const float*)d_in[29];
  float* out = (float*)d_out;

  float *FT = nullptr, *TP = nullptr, *YB = nullptr;
  cudaGetSymbolAddress((void**)&FT, g_feat);
  cudaGetSymbolAddress((void**)&TP, g_temp);
  cudaGetSymbolAddress((void**)&YB, g_Y);

  cudaFuncSetAttribute(gemm128_kernel,
                       cudaFuncAttributeMaxDynamicSharedMemorySize,
                       SMEM_GEMM_BYTES);

  const int GEMM_GRID = N / 64;       // 2048
  const int ROW_GRID  = N / 8;        // 16384 (warp per row, 8 rows/block)
  const int MLP_GRID  = (N * C) / 256;

  // ---- Input stage: feat = relu(GN(relu(ctrs@w0+b0)@w1) + GN(relu(feats@w0+b0)@w1))
  mlp0_kernel<<<MLP_GRID, 256>>>(ctrs, ic_w0, ic_b0, TP);
  gemm128_kernel<<<GEMM_GRID, 256, SMEM_GEMM_BYTES>>>(TP, ic_w1, FT);
  mlp0_kernel<<<MLP_GRID, 256>>>(feats, if_w0, if_b0, TP);
  gemm128_kernel<<<GEMM_GRID, 256, SMEM_GEMM_BYTES>>>(TP, if_w1, YB);
  combine_kernel<<<ROW_GRID, 256>>>(FT, YB, ic_g, ic_bt, if_g, if_bt, FT);

  // ---- 4 fusion blocks
  for (int i = 0; i < NB; ++i) {
    // temp = feat @ ctr_w[i]
    gemm128_kernel<<<GEMM_GRID, 256, SMEM_GEMM_BYTES>>>(FT, ctr_w + (size_t)i * CC, TP);

    // pre: per scale, Y = feat @ pre_w[i,s]; temp[pre_u] += Y[pre_v]
    for (int s = 0; s < S; ++s) {
      gemm128_kernel<<<GEMM_GRID, 256, SMEM_GEMM_BYTES>>>(
          FT, pre_w + (size_t)(i * S + s) * CC, YB);
      scatter_kernel<<<(E * 32) / 256, 256>>>(YB, pre_u + (size_t)s * E,
                                              pre_v + (size_t)s * E, E, TP);
    }
    // suc
    for (int s = 0; s < S; ++s) {
      gemm128_kernel<<<GEMM_GRID, 256, SMEM_GEMM_BYTES>>>(
          FT, suc_w + (size_t)(i * S + s) * CC, YB);
      scatter_kernel<<<(E * 32) / 256, 256>>>(YB, suc_u + (size_t)s * E,
                                              suc_v + (size_t)s * E, E, TP);
    }
    // left / right
    gemm128_kernel<<<GEMM_GRID, 256, SMEM_GEMM_BYTES>>>(FT, left_w + (size_t)i * CC, YB);
    scatter_kernel<<<(EL * 32) / 256, 256>>>(YB, left_u, left_v, EL, TP);
    gemm128_kernel<<<GEMM_GRID, 256, SMEM_GEMM_BYTES>>>(FT, right_w + (size_t)i * CC, YB);
    scatter_kernel<<<(EL * 32) / 256, 256>>>(YB, right_u, right_v, EL, TP);

    // feat_mid = relu(GN(temp))
    gn_relu_kernel<<<ROW_GRID, 256>>>(TP, norm_g + (size_t)i * C,
                                      norm_b + (size_t)i * C, YB);
    // Y2 = feat_mid @ ctr2_w[i]
    gemm128_kernel<<<GEMM_GRID, 256, SMEM_GEMM_BYTES>>>(YB, ctr2_w + (size_t)i * CC, TP);
    // feat = relu(GN(Y2) + identity)   (identity == feat at block entry)
    float* dst = (i == NB - 1) ? out : FT;
    gn_res_relu_kernel<<<ROW_GRID, 256>>>(TP, ctr2_g + (size_t)i * C,
                                          ctr2_b + (size_t)i * C, FT, dst);
  }
}

// round 3
// speedup vs baseline: 1.5000x; 1.5000x over previous
#include <cuda_runtime.h>
#include <cuda_bf16.h>
#include <cstdint>

#define DEV_INLINE __device__ __forceinline__
using bf16 = __nv_bfloat16;

constexpr int N  = 131072;
constexpr int C  = 128;
constexpr int S  = 6;
constexpr int E  = 131072;
constexpr int EL = 32768;
constexpr int NB = 4;
constexpr int CC = C * C;
constexpr int NSLOT = 66;

// Scratch (allocation-free rule: static __device__ arrays)
__device__ float g_feat[N * C];
__device__ float g_temp[N * C];
__device__ float g_Y[N * C];
__device__ bf16  g_Ah[N * C];
__device__ bf16  g_Al[N * C];
__device__ bf16  g_Wh[NSLOT * CC];   // [slot][c][k] (transposed)
__device__ bf16  g_Wl[NSLOT * CC];

DEV_INLINE uint32_t smem_u32(const void* p) {
  uint32_t a;
  asm("{ .reg .u64 t; cvta.to.shared.u64 t, %1; cvt.u32.u64 %0, t; }"
      : "=r"(a) : "l"(p));
  return a;
}

// ---------------------------------------------------------------------------
// mma.sync GEMM: Out[N,128] = (Ah+Al) @ (Wh+Wl)^T, 3 passes (hh, hl, lh).
// CTA 128x128, 256 threads / 8 warps, warp tile 64x32.
// smem: 4 tiles of 128x128 bf16, 256B rows, XOR-16B swizzle on (row&7).
// ---------------------------------------------------------------------------
constexpr int TILE_BYTES = 128 * 256;               // 32 KB
constexpr int SMEM_MMA_BYTES = 4 * TILE_BYTES;      // 128 KB

DEV_INLINE void ldsm4(uint32_t& r0, uint32_t& r1, uint32_t& r2, uint32_t& r3,
                      uint32_t addr) {
  asm volatile("ldmatrix.sync.aligned.m8n8.x4.shared.b16 {%0,%1,%2,%3}, [%4];"
               : "=r"(r0), "=r"(r1), "=r"(r2), "=r"(r3) : "r"(addr));
}
DEV_INLINE void mma_bf16(float* c, uint32_t a0, uint32_t a1, uint32_t a2,
                         uint32_t a3, uint32_t b0, uint32_t b1) {
  asm volatile(
      "mma.sync.aligned.m16n8k16.row.col.f32.bf16.bf16.f32 "
      "{%0,%1,%2,%3}, {%4,%5,%6,%7}, {%8,%9}, {%0,%1,%2,%3};"
      : "+f"(c[0]), "+f"(c[1]), "+f"(c[2]), "+f"(c[3])
      : "r"(a0), "r"(a1), "r"(a2), "r"(a3), "r"(b0), "r"(b1));
}

__global__ void __launch_bounds__(256, 1) gemm_mma(
    const bf16* __restrict__ Ah, const bf16* __restrict__ Al,
    const bf16* __restrict__ Bh, const bf16* __restrict__ Bl,
    float* __restrict__ Out) {
  extern __shared__ __align__(16) char smem[];
  const uint32_t sbase = smem_u32(smem);
  const int tid = threadIdx.x, lane = tid & 31, wid = tid >> 5;
  const int rowBase = blockIdx.x * 128;

  // ---- stage 4 tiles (coalesced 16B reads, swizzled 16B smem writes) ----
  const bf16* srcs[4] = {Ah + (size_t)rowBase * C, Al + (size_t)rowBase * C,
                         Bh, Bl};
#pragma unroll
  for (int m = 0; m < 4; ++m) {
    char* dst = smem + m * TILE_BYTES;
    const uint4* src = (const uint4*)srcs[m];
#pragma unroll
    for (int t = 0; t < 8; ++t) {
      int idx = tid + t * 256;           // 0..2047 (16B chunks)
      int r = idx >> 4, c16 = idx & 15;
      uint32_t off = r * 256 + ((c16 * 16) ^ ((r & 7) << 4));
      *(uint4*)(dst + off) = src[idx];
    }
  }
  __syncthreads();

  // warp tile: rows rw..rw+63, cols cw..cw+31
  const int rw = (wid & 1) * 64;
  const int cw = (wid >> 1) * 32;

  float acc[4][4][4];  // [mi][ni][frag]
#pragma unroll
  for (int mi = 0; mi < 4; ++mi)
#pragma unroll
    for (int ni = 0; ni < 4; ++ni)
#pragma unroll
      for (int j = 0; j < 4; ++j) acc[mi][ni][j] = 0.0f;

  // per-lane ldmatrix address components (within a tile)
  // A: row = rw + mi*16 + (lane&15), colByte = kb + (lane>>4)*16
  uint32_t aRow[4], aColK = (lane >> 4) * 16;
#pragma unroll
  for (int mi = 0; mi < 4; ++mi) aRow[mi] = rw + mi * 16 + (lane & 15);
  // B: n = cw + bi*16 + (lane>>4)*8 + (lane&7), colByte = kb + ((lane>>3)&1)*16
  uint32_t bRow[2], bColK = ((lane >> 3) & 1) * 16;
#pragma unroll
  for (int bi = 0; bi < 2; ++bi)
    bRow[bi] = cw + bi * 16 + ((lane >> 4) * 8) + (lane & 7);

  const uint32_t aTile[3] = {0, 0, TILE_BYTES};                    // hh, hl, lh
  const uint32_t bTile[3] = {2 * TILE_BYTES, 3 * TILE_BYTES, 2 * TILE_BYTES};

#pragma unroll
  for (int p = 0; p < 3; ++p) {
    const uint32_t aBase = sbase + aTile[p];
    const uint32_t bBase = sbase + bTile[p];
#pragma unroll
    for (int kk = 0; kk < 8; ++kk) {
      const uint32_t kb = kk * 32;
      uint32_t a[4][4];
#pragma unroll
      for (int mi = 0; mi < 4; ++mi) {
        uint32_t r = aRow[mi];
        uint32_t addr = aBase + r * 256 + (((kb | aColK)) ^ ((r & 7) << 4));
        ldsm4(a[mi][0], a[mi][1], a[mi][2], a[mi][3], addr);
      }
      uint32_t b[4][2];
#pragma unroll
      for (int bi = 0; bi < 2; ++bi) {
        uint32_t r = bRow[bi];
        uint32_t addr = bBase + r * 256 + (((kb | bColK)) ^ ((r & 7) << 4));
        ldsm4(b[bi * 2][0], b[bi * 2][1], b[bi * 2 + 1][0], b[bi * 2 + 1][1],
              addr);
      }
#pragma unroll
      for (int mi = 0; mi < 4; ++mi)
#pragma unroll
        for (int ni = 0; ni < 4; ++ni)
          mma_bf16(acc[mi][ni], a[mi][0], a[mi][1], a[mi][2], a[mi][3],
                   b[ni][0], b[ni][1]);
    }
  }

  // ---- epilogue: direct float2 stores ----
  const int r0 = lane >> 2, c0 = (lane & 3) * 2;
#pragma unroll
  for (int mi = 0; mi < 4; ++mi) {
#pragma unroll
    for (int ni = 0; ni < 4; ++ni) {
      int grow = rowBase + rw + mi * 16 + r0;
      int gcol = cw + ni * 8 + c0;
      *(float2*)(Out + (size_t)grow * C + gcol) =
          make_float2(acc[mi][ni][0], acc[mi][ni][1]);
      *(float2*)(Out + (size_t)(grow + 8) * C + gcol) =
          make_float2(acc[mi][ni][2], acc[mi][ni][3]);
    }
  }
}

// ---------------------------------------------------------------------------
// split helpers
// ---------------------------------------------------------------------------
DEV_INLINE void split_store4(bf16* Hh, bf16* Hl, size_t idx4, float4 o) {
  __nv_bfloat162 h0 = __floats2bfloat162_rn(o.x, o.y);
  __nv_bfloat162 h1 = __floats2bfloat162_rn(o.z, o.w);
  float lx = o.x - __bfloat162float(h0.x);
  float ly = o.y - __bfloat162float(h0.y);
  float lz = o.z - __bfloat162float(h1.x);
  float lw = o.w - __bfloat162float(h1.y);
  __nv_bfloat162 l0 = __floats2bfloat162_rn(lx, ly);
  __nv_bfloat162 l1 = __floats2bfloat162_rn(lz, lw);
  *(uint2*)(Hh + idx4) = make_uint2(*(uint32_t*)&h0, *(uint32_t*)&h1);
  *(uint2*)(Hl + idx4) = make_uint2(*(uint32_t*)&l0, *(uint32_t*)&l1);
}

// Weight split + transpose: out[slot][c][k] = split(src[m][k][c])
__global__ void wsplit_kernel(const float* __restrict__ src, int slotBase, int nm) {
  int idx = blockIdx.x * 256 + threadIdx.x;
  int m = idx >> 14, r = idx & 16383;
  int c = r >> 7, k = r & 127;
  float w = src[(size_t)m * CC + k * 128 + c];
  bf16 hi = __float2bfloat16(w);
  bf16 lo = __float2bfloat16(w - __bfloat162float(hi));
  size_t o = (size_t)(slotBase + m) * CC + r;
  g_Wh[o] = hi;
  g_Wl[o] = lo;
}

__global__ void mlp0_split_kernel(const float* __restrict__ X2,
                                  const float* __restrict__ W0,
                                  const float* __restrict__ B0,
                                  bf16* __restrict__ Hh, bf16* __restrict__ Hl) {
  int idx = blockIdx.x * 256 + threadIdx.x;  // N*64
  int n = idx >> 6, c = (idx & 63) << 1;
  float x0 = X2[2 * n], x1 = X2[2 * n + 1];
  float ha = fmaxf(fmaf(x0, W0[c], fmaf(x1, W0[C + c], B0[c])), 0.0f);
  float hb = fmaxf(fmaf(x0, W0[c + 1], fmaf(x1, W0[C + c + 1], B0[c + 1])), 0.0f);
  __nv_bfloat162 h = __floats2bfloat162_rn(ha, hb);
  __nv_bfloat162 l = __floats2bfloat162_rn(ha - __bfloat162float(h.x),
                                           hb - __bfloat162float(h.y));
  *(__nv_bfloat162*)(Hh + (size_t)n * C + c) = h;
  *(__nv_bfloat162*)(Hl + (size_t)n * C + c) = l;
}

// ---------------------------------------------------------------------------
// Scatter: T[u[e], :] += Y[v[e], :]
// ---------------------------------------------------------------------------
__global__ void scatter_kernel(const float* __restrict__ Y,
                               const int* __restrict__ u,
                               const int* __restrict__ v, int nE,
                               float* __restrict__ T) {
  int e = (blockIdx.x * blockDim.x + threadIdx.x) >> 5;
  if (e >= nE) return;
  int lane = threadIdx.x & 31;
  int src = __ldg(&v[e]);
  int dst = __ldg(&u[e]);
  float4 val = ((const float4*)(Y + (size_t)src * C))[lane];
  float* p = T + (size_t)dst * C + lane * 4;
  asm volatile("red.global.add.v4.f32 [%0], {%1, %2, %3, %4};"
               :: "l"(p), "f"(val.x), "f"(val.y), "f"(val.z), "f"(val.w)
               : "memory");
}

// ---------------------------------------------------------------------------
// GroupNorm kernels (warp per row, 4 channels per lane)
// ---------------------------------------------------------------------------
DEV_INLINE float wsum(float v) {
#pragma unroll
  for (int o = 16; o > 0; o >>= 1) v += __shfl_xor_sync(0xffffffffu, v, o);
  return v;
}

__global__ void gn_relu_split_kernel(const float* __restrict__ X,
                                     const float* __restrict__ G,
                                     const float* __restrict__ Bt,
                                     bf16* __restrict__ Hh, bf16* __restrict__ Hl) {
  int w = (blockIdx.x * blockDim.x + threadIdx.x) >> 5;
  int lane = threadIdx.x & 31;
  float4 x = ((const float4*)X)[(size_t)w * 32 + lane];
  float s = wsum(x.x + x.y + x.z + x.w);
  float q = wsum(x.x * x.x + x.y * x.y + x.z * x.z + x.w * x.w);
  float mu = s * (1.0f / 128.0f);
  float rs = rsqrtf(q * (1.0f / 128.0f) - mu * mu + 1e-5f);
  float4 g = ((const float4*)G)[lane];
  float4 b = ((const float4*)Bt)[lane];
  float4 o;
  o.x = fmaxf((x.x - mu) * rs * g.x + b.x, 0.0f);
  o.y = fmaxf((x.y - mu) * rs * g.y + b.y, 0.0f);
  o.z = fmaxf((x.z - mu) * rs * g.z + b.z, 0.0f);
  o.w = fmaxf((x.w - mu) * rs * g.w + b.w, 0.0f);
  split_store4(Hh, Hl, ((size_t)w * 32 + lane) * 4, o);
}

__global__ void gn_res_relu_kernel(const float* __restrict__ X,
                                   const float* __restrict__ G,
                                   const float* __restrict__ Bt,
                                   const float* __restrict__ Id,
                                   float* __restrict__ Of,
                                   bf16* __restrict__ Hh, bf16* __restrict__ Hl) {
  int w = (blockIdx.x * blockDim.x + threadIdx.x) >> 5;
  int lane = threadIdx.x & 31;
  float4 x = ((const float4*)X)[(size_t)w * 32 + lane];
  float s = wsum(x.x + x.y + x.z + x.w);
  float q = wsum(x.x * x.x + x.y * x.y + x.z * x.z + x.w * x.w);
  float mu = s * (1.0f / 128.0f);
  float rs = rsqrtf(q * (1.0f / 128.0f) - mu * mu + 1e-5f);
  float4 g = ((const float4*)G)[lane];
  float4 b = ((const float4*)Bt)[lane];
  float4 id = ((const float4*)Id)[(size_t)w * 32 + lane];
  float4 o;
  o.x = fmaxf((x.x - mu) * rs * g.x + b.x + id.x, 0.0f);
  o.y = fmaxf((x.y - mu) * rs * g.y + b.y + id.y, 0.0f);
  o.z = fmaxf((x.z - mu) * rs * g.z + b.z + id.z, 0.0f);
  o.w = fmaxf((x.w - mu) * rs * g.w + b.w + id.w, 0.0f);
  ((float4*)Of)[(size_t)w * 32 + lane] = o;
  if (Hh) split_store4(Hh, Hl, ((size_t)w * 32 + lane) * 4, o);
}

__global__ void combine_kernel(const float* __restrict__ Y1,
                               const float* __restrict__ Y2,
                               const float* __restrict__ G1,
                               const float* __restrict__ B1,
                               const float* __restrict__ G2,
                               const float* __restrict__ B2,
                               float* __restrict__ Of,
                               bf16* __restrict__ Hh, bf16* __restrict__ Hl) {
  int w = (blockIdx.x * blockDim.x + threadIdx.x) >> 5;
  int lane = threadIdx.x & 31;
  float4 x1 = ((const float4*)Y1)[(size_t)w * 32 + lane];
  float4 x2 = ((const float4*)Y2)[(size_t)w * 32 + lane];
  float s1 = wsum(x1.x + x1.y + x1.z + x1.w);
  float q1 = wsum(x1.x * x1.x + x1.y * x1.y + x1.z * x1.z + x1.w * x1.w);
  float s2 = wsum(x2.x + x2.y + x2.z + x2.w);
  float q2 = wsum(x2.x * x2.x + x2.y * x2.y + x2.z * x2.z + x2.w * x2.w);
  float mu1 = s1 * (1.0f / 128.0f);
  float rs1 = rsqrtf(q1 * (1.0f / 128.0f) - mu1 * mu1 + 1e-5f);
  float mu2 = s2 * (1.0f / 128.0f);
  float rs2 = rsqrtf(q2 * (1.0f / 128.0f) - mu2 * mu2 + 1e-5f);
  float4 g1 = ((const float4*)G1)[lane];
  float4 b1 = ((const float4*)B1)[lane];
  float4 g2 = ((const float4*)G2)[lane];
  float4 b2 = ((const float4*)B2)[lane];
  float4 o;
  o.x = fmaxf((x1.x - mu1) * rs1 * g1.x + b1.x + (x2.x - mu2) * rs2 * g2.x + b2.x, 0.0f);
  o.y = fmaxf((x1.y - mu1) * rs1 * g1.y + b1.y + (x2.y - mu2) * rs2 * g2.y + b2.y, 0.0f);
  o.z = fmaxf((x1.z - mu1) * rs1 * g1.z + b1.z + (x2.z - mu2) * rs2 * g2.z + b2.z, 0.0f);
  o.w = fmaxf((x1.w - mu1) * rs1 * g1.w + b1.w + (x2.w - mu2) * rs2 * g2.w + b2.w, 0.0f);
  ((float4*)Of)[(size_t)w * 32 + lane] = o;
  split_store4(Hh, Hl, ((size_t)w * 32 + lane) * 4, o);
}

// ---------------------------------------------------------------------------
extern "C" void kernel_launch(void* const* d_in, const int* in_sizes, int n_in,
                              void* d_out, int out_size) {
  const float* ctrs   = (const float*)d_in[0];
  const float* feats  = (const float*)d_in[1];
  const int*   pre_u  = (const int*)d_in[2];
  const int*   pre_v  = (const int*)d_in[3];
  const int*   suc_u  = (const int*)d_in[4];
  const int*   suc_v  = (const int*)d_in[5];
  const int*   left_u = (const int*)d_in[6];
  const int*   left_v = (const int*)d_in[7];
  const int*   right_u= (const int*)d_in[8];
  const int*   right_v= (const int*)d_in[9];
  const float* ic_w0  = (const float*)d_in[10];
  const float* ic_b0  = (const float*)d_in[11];
  const float* ic_w1  = (const float*)d_in[12];
  const float* ic_g   = (const float*)d_in[13];
  const float* ic_bt  = (const float*)d_in[14];
  const float* if_w0  = (const float*)d_in[15];
  const float* if_b0  = (const float*)d_in[16];
  const float* if_w1  = (const float*)d_in[17];
  const float* if_g   = (const float*)d_in[18];
  const float* if_bt  = (const float*)d_in[19];
  const float* ctr_w  = (const float*)d_in[20];
  const float* pre_w  = (const float*)d_in[21];
  const float* suc_w  = (const float*)d_in[22];
  const float* left_w = (const float*)d_in[23];
  const float* right_w= (const float*)d_in[24];
  const float* norm_g = (const float*)d_in[25];
  const float* norm_b = (const float*)d_in[26];
  const float* ctr2_w = (const float*)d_in[27];
  const float* ctr2_g = (const float*)d_in[28];
  const float* ctr2_b = (const float*)d_in[29];
  float* out = (float*)d_out;

  float *FT, *TP, *YB;
  bf16 *AH, *AL, *WH, *WL;
  cudaGetSymbolAddress((void**)&FT, g_feat);
  cudaGetSymbolAddress((void**)&TP, g_temp);
  cudaGetSymbolAddress((void**)&YB, g_Y);
  cudaGetSymbolAddress((void**)&AH, g_Ah);
  cudaGetSymbolAddress((void**)&AL, g_Al);
  cudaGetSymbolAddress((void**)&WH, g_Wh);
  cudaGetSymbolAddress((void**)&WL, g_Wl);

  cudaFuncSetAttribute(gemm_mma, cudaFuncAttributeMaxDynamicSharedMemorySize,
                       SMEM_MMA_BYTES);

  const int GEMM_GRID = N / 128;      // 1024
  const int ROW_GRID  = N / 8;        // 16384
  const int MLP_GRID  = (N * 64) / 256;

  // ---- weight split + transpose ----
  wsplit_kernel<<<1 * 64, 256>>>(ic_w1, 0, 1);
  wsplit_kernel<<<1 * 64, 256>>>(if_w1, 1, 1);
  wsplit_kernel<<<4 * 64, 256>>>(ctr_w, 2, 4);
  wsplit_kernel<<<24 * 64, 256>>>(pre_w, 6, 24);
  wsplit_kernel<<<24 * 64, 256>>>(suc_w, 30, 24);
  wsplit_kernel<<<4 * 64, 256>>>(left_w, 54, 4);
  wsplit_kernel<<<4 * 64, 256>>>(right_w, 58, 4);
  wsplit_kernel<<<4 * 64, 256>>>(ctr2_w, 62, 4);

#define GEMM(slot, OutPtr)                                                     \
  gemm_mma<<<GEMM_GRID, 256, SMEM_MMA_BYTES>>>(AH, AL, WH + (size_t)(slot) * CC, \
                                               WL + (size_t)(slot) * CC, OutPtr)

  // ---- Input stage ----
  mlp0_split_kernel<<<MLP_GRID, 256>>>(ctrs, ic_w0, ic_b0, AH, AL);
  GEMM(0, FT);
  mlp0_split_kernel<<<MLP_GRID, 256>>>(feats, if_w0, if_b0, AH, AL);
  GEMM(1, YB);
  combine_kernel<<<ROW_GRID, 256>>>(FT, YB, ic_g, ic_bt, if_g, if_bt, FT, AH, AL);

  // ---- 4 fusion blocks ----
  for (int i = 0; i < NB; ++i) {
    GEMM(2 + i, TP);  // temp = feat @ ctr_w[i]

    for (int s = 0; s < S; ++s) {
      GEMM(6 + i * S + s, YB);
      scatter_kernel<<<(E * 32) / 256, 256>>>(YB, pre_u + (size_t)s * E,
                                              pre_v + (size_t)s * E, E, TP);
    }
    for (int s = 0; s < S; ++s) {
      GEMM(30 + i * S + s, YB);
      scatter_kernel<<<(E * 32) / 256, 256>>>(YB, suc_u + (size_t)s * E,
                                              suc_v + (size_t)s * E, E, TP);
    }
    GEMM(54 + i, YB);
    scatter_kernel<<<(EL * 32) / 256, 256>>>(YB, left_u, left_v, EL, TP);
    GEMM(58 + i, YB);
    scatter_kernel<<<(EL * 32) / 256, 256>>>(YB, right_u, right_v, EL, TP);

    gn_relu_split_kernel<<<ROW_GRID, 256>>>(TP, norm_g + (size_t)i * C,
                                            norm_b + (size_t)i * C, AH, AL);
    GEMM(62 + i, TP);  // Y2 = feat_mid @ ctr2_w[i]

    if (i == NB - 1) {
      gn_res_relu_kernel<<<ROW_GRID, 256>>>(TP, ctr2_g + (size_t)i * C,
                                            ctr2_b + (size_t)i * C, FT, out,
                                            nullptr, nullptr);
    } else {
      gn_res_relu_kernel<<<ROW_GRID, 256>>>(TP, ctr2_g + (size_t)i * C,
                                            ctr2_b + (size_t)i * C, FT, FT,
                                            AH, AL);
    }
  }
#undef GEMM
}